// round 15
// baseline (speedup 1.0000x reference)
#include <cuda_runtime.h>
#include <cuda_fp16.h>
#include <math.h>
#include <stdint.h>

// ---------------- problem constants ----------------
#define D_MODEL 768
#define D_STATE 16
#define D_CONV  4
#define INNER   1536
#define N2      (2*INNER)     // 3072
#define BATCH   2
#define SEQLEN  2048
#define NTOK    (BATCH*SEQLEN)  // 4096
#define NCHUNK  64
#define CHUNK   (SEQLEN/NCHUNK) // 32
#define CT      8               // conv timesteps per thread

// ---------------- scratch (static device globals; no allocation) ----------------
__device__ float g_hend[BATCH*NCHUNK*D_STATE*INNER];   // general fallback
__device__ float g_h0  [BATCH*NCHUNK*D_STATE*INNER];   // general fallback
__device__ float g_hend_s[BATCH*NCHUNK*INNER];         // scalar fast path
__device__ float g_h0_s  [BATCH*NCHUNK*INNER];         // scalar fast path
__device__ float g_sdt [BATCH*NCHUNK*INNER];

// fp16 tensors
__device__ __half g_xp_h  [NTOK * INNER];
__device__ __half g_z_h   [NTOK * INNER];
__device__ __half g_hid_hi[NTOK * D_MODEL];
__device__ __half g_wi_hi [N2 * D_MODEL];
__device__ __half g_wd_hi [INNER * INNER];
__device__ __half g_wo_hi [D_MODEL * INNER];
__device__ __half g_u_hi  [NTOK * INNER];
__device__ __half g_dt_h  [NTOK * INNER];
__device__ __half g_yg_hi [NTOK * INNER];

// ---------------- helpers ----------------
__device__ __forceinline__ float siluf(float x) {
    return x * (1.0f / (1.0f + __expf(-x)));
}
__device__ __forceinline__ float softplusf(float x) {
    return fmaxf(x, 0.0f) + log1pf(__expf(-fabsf(x)));
}
__device__ __forceinline__ uint32_t smem_u32(const void* p) {
    uint32_t a;
    asm("{ .reg .u64 t; cvta.to.shared.u64 t, %1; cvt.u32.u64 %0, t; }"
        : "=r"(a) : "l"(p));
    return a;
}
__device__ __forceinline__ void cp16(uint32_t s, const void* g) {
    asm volatile("cp.async.cg.shared.global [%0], [%1], 16;\n" :: "r"(s), "l"(g));
}
__device__ __forceinline__ void cp_commit() {
    asm volatile("cp.async.commit_group;\n");
}
template<int N> __device__ __forceinline__ void cp_wait() {
    asm volatile("cp.async.wait_group %0;\n" :: "n"(N));
}
__device__ __forceinline__ void ldm_x4(uint32_t a, uint32_t* r) {
    asm volatile("ldmatrix.sync.aligned.m8n8.x4.shared.b16 {%0,%1,%2,%3}, [%4];"
                 : "=r"(r[0]), "=r"(r[1]), "=r"(r[2]), "=r"(r[3]) : "r"(a));
}
__device__ __forceinline__ void mma_fp16(float* d, const uint32_t* a,
                                         uint32_t b0, uint32_t b1) {
    asm volatile(
        "mma.sync.aligned.m16n8k16.row.col.f32.f16.f16.f32 "
        "{%0,%1,%2,%3}, {%4,%5,%6,%7}, {%8,%9}, {%0,%1,%2,%3};\n"
        : "+f"(d[0]), "+f"(d[1]), "+f"(d[2]), "+f"(d[3])
        : "r"(a[0]), "r"(a[1]), "r"(a[2]), "r"(a[3]), "r"(b0), "r"(b1));
}
__device__ __forceinline__ void store_h4(__half* p, float4 v) {
    __half2 a = __floats2half2_rn(v.x, v.y);
    __half2 b = __floats2half2_rn(v.z, v.w);
    uint2 o;
    o.x = *(uint32_t*)&a;
    o.y = *(uint32_t*)&b;
    *(uint2*)p = o;
}

// ---------------- merged split kernel (all plain fp32 -> fp16) ----------------
#define SPL_N0 (NTOK*D_MODEL)
#define SPL_N1 (N2*D_MODEL)
#define SPL_N2 (INNER*INNER)
#define SPL_N3 (D_MODEL*INNER)
#define SPL_TOT4 ((SPL_N0+SPL_N1+SPL_N2+SPL_N3)/4)

__device__ __forceinline__ void cvt4_hi(const float* s, __half* h) {
    float4 v = *(const float4*)s;
    store_h4(h, v);
}

__global__ __launch_bounds__(256)
void split_all(const float* __restrict__ hidden, const float* __restrict__ wi,
               const float* __restrict__ wd, const float* __restrict__ wo,
               __half* __restrict__ hid_hi, __half* __restrict__ wi_hi,
               __half* __restrict__ wd_hi, __half* __restrict__ wo_hi)
{
    int idx = (blockIdx.x * blockDim.x + threadIdx.x) * 4;
    if (idx < SPL_N0) {
        cvt4_hi(hidden + idx, hid_hi + idx);
    } else if ((idx -= SPL_N0) < SPL_N1) {
        cvt4_hi(wi + idx, wi_hi + idx);
    } else if ((idx -= SPL_N1) < SPL_N2) {
        cvt4_hi(wd + idx, wd_hi + idx);
    } else if ((idx -= SPL_N2) < SPL_N3) {
        cvt4_hi(wo + idx, wo_hi + idx);
    }
}

// ---------------- fp16 x1 NT GEMM (CTA 128x256, warptile 64x64, 3-stage) ----------------
// EPI 1: softplus(x+b1+b2) -> fp16 into Ca (stride INNER)
// EPI 2: in_proj mixed: cols < INNER -> fp16 Ca; cols >= INNER -> fp16 Cb
#define TILE_A_B 16384               // 128 rows x 128 bytes
#define TILE_B_B 32768               // 256 rows x 128 bytes
#define GSTAGE (TILE_A_B + TILE_B_B) // 49152
#define SMEM_G (3 * GSTAGE)          // 147456

template<int EPI>
__global__ __launch_bounds__(256, 1)
void gemm_fp16x(const __half* __restrict__ Ahi, const __half* __restrict__ Bhi,
                __half* __restrict__ Ca, __half* __restrict__ Cb,
                int M, int K,
                const float* __restrict__ b1, const float* __restrict__ b2)
{
    extern __shared__ char smem[];
    const uint32_t sb = smem_u32(smem);

    const int tid  = threadIdx.x;
    const int wid  = tid >> 5;
    const int lane = tid & 31;
    const int wm   = wid & 1;     // rows wm*64
    const int wn   = wid >> 1;    // cols wn*64
    const int g    = lane >> 3;
    const int lr   = lane & 7;

    const int row0 = blockIdx.y * 128;
    const int col0 = blockIdx.x * 256;

    const __half* srcA = Ahi + (size_t)row0 * K;
    const __half* srcB = Bhi + (size_t)col0 * K;

    float acc[4][8][4];
    #pragma unroll
    for (int mt = 0; mt < 4; ++mt)
        #pragma unroll
        for (int nt = 0; nt < 8; ++nt)
            #pragma unroll
            for (int r = 0; r < 4; ++r) acc[mt][nt][r] = 0.0f;

    auto load_stage = [&](int s, int kc) {
        uint32_t dstA = sb + (uint32_t)s * GSTAGE;
        uint32_t dstB = dstA + TILE_A_B;
        const __half* sA = srcA + kc;
        const __half* sB = srcB + kc;
        #pragma unroll
        for (int i = 0; i < 4; ++i) {
            int c = tid + i * 256;
            int r = c >> 3, ch = c & 7;
            cp16(dstA + r * 128 + ((ch ^ (r & 7)) << 4),
                 sA + (size_t)r * K + ch * 8);
        }
        #pragma unroll
        for (int i = 0; i < 8; ++i) {
            int c = tid + i * 256;
            int r = c >> 3, ch = c & 7;
            cp16(dstB + r * 128 + ((ch ^ (r & 7)) << 4),
                 sB + (size_t)r * K + ch * 8);
        }
    };

    const int KT = K / 64;
    load_stage(0, 0); cp_commit();
    load_stage(1, 64); cp_commit();

    int st = 0;
    for (int kt = 0; kt < KT; ++kt) {
        if (kt + 1 < KT) cp_wait<1>(); else cp_wait<0>();
        __syncthreads();
        if (kt + 2 < KT) {
            int ns = st + 2; if (ns >= 3) ns -= 3;
            load_stage(ns, (kt + 2) * 64);
            cp_commit();
        }

        const uint32_t sAh = sb + (uint32_t)st * GSTAGE;
        const uint32_t sBh = sAh + TILE_A_B;

        #pragma unroll
        for (int k16 = 0; k16 < 4; ++k16) {
            const int c0 = k16 * 2;
            const int arow_off = ((g & 1) << 3) + lr;
            const int ach = c0 + (g >> 1);
            const int brow_off = ((g >> 1) << 3) + lr;
            const int bch = c0 + (g & 1);

            uint32_t ah[4][4];
            #pragma unroll
            for (int mt = 0; mt < 4; ++mt) {
                int row = wm * 64 + mt * 16 + arow_off;
                uint32_t off = row * 128 + (((ach ^ (row & 7))) << 4);
                ldm_x4(sAh + off, ah[mt]);
            }
            uint32_t bh[8][2];
            #pragma unroll
            for (int nn = 0; nn < 4; ++nn) {
                int row = wn * 64 + nn * 16 + brow_off;
                uint32_t off = row * 128 + (((bch ^ (row & 7))) << 4);
                uint32_t t4[4];
                ldm_x4(sBh + off, t4);
                bh[nn*2][0] = t4[0]; bh[nn*2][1] = t4[1];
                bh[nn*2+1][0] = t4[2]; bh[nn*2+1][1] = t4[3];
            }
            #pragma unroll
            for (int mt = 0; mt < 4; ++mt)
                #pragma unroll
                for (int nt = 0; nt < 8; ++nt)
                    mma_fp16(acc[mt][nt], ah[mt], bh[nt][0], bh[nt][1]);
        }
        if (++st == 3) st = 0;
    }

    const int qr = lane >> 2;
    const int qc = (lane & 3) * 2;
    #pragma unroll
    for (int mt = 0; mt < 4; ++mt) {
        #pragma unroll
        for (int nt = 0; nt < 8; ++nt) {
            int gr = row0 + wm * 64 + mt * 16 + qr;
            int gc = col0 + wn * 64 + nt * 8 + qc;
            float v0 = acc[mt][nt][0], v1 = acc[mt][nt][1];
            float v2 = acc[mt][nt][2], v3 = acc[mt][nt][3];
            if (EPI == 1) {
                float e0 = b1[gc] + b2[gc];
                float e1 = b1[gc + 1] + b2[gc + 1];
                *(__half2*)&Ca[(size_t)gr * INNER + gc] =
                    __floats2half2_rn(softplusf(v0 + e0), softplusf(v1 + e1));
                *(__half2*)&Ca[(size_t)(gr + 8) * INNER + gc] =
                    __floats2half2_rn(softplusf(v2 + e0), softplusf(v3 + e1));
            } else {  // EPI == 2
                __half* Cp = (gc < INNER) ? Ca : Cb;
                int g2 = (gc < INNER) ? gc : gc - INNER;
                *(__half2*)&Cp[(size_t)gr * INNER + g2] = __floats2half2_rn(v0, v1);
                *(__half2*)&Cp[(size_t)(gr + 8) * INNER + g2] = __floats2half2_rn(v2, v3);
            }
        }
    }
}

// ---------------- out_proj GEMM: 64x64 tiles, x1, 3-stage, 3 CTAs/SM ----------------
#define OTILE 8192
#define OSTAGE (2 * OTILE)
#define OSMEM (3 * OSTAGE)     // 49152

__global__ __launch_bounds__(256, 3)
void gemm_out64(const __half* __restrict__ Ahi, const __half* __restrict__ Bhi,
                float* __restrict__ C, int M, int N, int K)
{
    extern __shared__ char smem[];
    const uint32_t sb = smem_u32(smem);

    const int tid  = threadIdx.x;
    const int wid  = tid >> 5;
    const int lane = tid & 31;
    const int wm   = wid & 1;
    const int wn   = wid >> 1;
    const int g    = lane >> 3;
    const int lr   = lane & 7;

    const int row0 = blockIdx.y * 64;
    const int col0 = blockIdx.x * 64;

    const __half* sA  = Ahi + (size_t)row0 * K;
    const __half* sBh = Bhi + (size_t)col0 * K;

    float acc[2][2][4];
    #pragma unroll
    for (int mt = 0; mt < 2; ++mt)
        #pragma unroll
        for (int nt = 0; nt < 2; ++nt)
            #pragma unroll
            for (int r = 0; r < 4; ++r) acc[mt][nt][r] = 0.0f;

    auto load_stage = [&](int s, int kc) {
        uint32_t base = sb + (uint32_t)s * OSTAGE;
        const __half* gp[2] = { sA + kc, sBh + kc };
        #pragma unroll
        for (int t = 0; t < 2; ++t) {
            uint32_t dst = base + (uint32_t)t * OTILE;
            const __half* src = gp[t];
            #pragma unroll
            for (int i = 0; i < 2; ++i) {
                int c = tid + i * 256;
                int r = c >> 3, ch = c & 7;
                cp16(dst + r * 128 + ((ch ^ (r & 7)) << 4),
                     src + (size_t)r * K + ch * 8);
            }
        }
    };

    const int KT = K / 64;   // 24
    load_stage(0, 0); cp_commit();
    load_stage(1, 64); cp_commit();

    int st = 0;
    for (int kt = 0; kt < KT; ++kt) {
        if (kt + 1 < KT) cp_wait<1>(); else cp_wait<0>();
        __syncthreads();
        if (kt + 2 < KT) {
            int ns = st + 2; if (ns >= 3) ns -= 3;
            load_stage(ns, (kt + 2) * 64);
            cp_commit();
        }

        const uint32_t base = sb + (uint32_t)st * OSTAGE;
        const uint32_t mA  = base;
        const uint32_t mBh = base + OTILE;

        #pragma unroll
        for (int k16 = 0; k16 < 4; ++k16) {
            const int c0 = k16 * 2;
            const int arow_off = ((g & 1) << 3) + lr;
            const int ach = c0 + (g >> 1);
            const int brow_off = ((g >> 1) << 3) + lr;
            const int bch = c0 + (g & 1);

            uint32_t ah[2][4];
            #pragma unroll
            for (int mt = 0; mt < 2; ++mt) {
                int row = wm * 32 + mt * 16 + arow_off;
                uint32_t off = row * 128 + (((ach ^ (row & 7))) << 4);
                ldm_x4(mA + off, ah[mt]);
            }
            uint32_t bh[2][2];
            {
                int row = wn * 16 + brow_off;
                uint32_t off = row * 128 + (((bch ^ (row & 7))) << 4);
                uint32_t t4[4];
                ldm_x4(mBh + off, t4);
                bh[0][0] = t4[0]; bh[0][1] = t4[1];
                bh[1][0] = t4[2]; bh[1][1] = t4[3];
            }
            #pragma unroll
            for (int mt = 0; mt < 2; ++mt)
                #pragma unroll
                for (int nt = 0; nt < 2; ++nt)
                    mma_fp16(acc[mt][nt], ah[mt], bh[nt][0], bh[nt][1]);
        }
        if (++st == 3) st = 0;
    }

    const int qr = lane >> 2;
    const int qc = (lane & 3) * 2;
    #pragma unroll
    for (int mt = 0; mt < 2; ++mt) {
        #pragma unroll
        for (int nt = 0; nt < 2; ++nt) {
            int gr = row0 + wm * 32 + mt * 16 + qr;
            int gc = col0 + wn * 16 + nt * 8 + qc;
            *(float2*)&C[(size_t)gr * N + gc] =
                make_float2(acc[mt][nt][0], acc[mt][nt][1]);
            *(float2*)&C[(size_t)(gr + 8) * N + gc] =
                make_float2(acc[mt][nt][2], acc[mt][nt][3]);
        }
    }
}

// ---------------- conv: 4 ch x 8 t, sliding window, fp16 in/out ----------------
__global__ __launch_bounds__(256)
void conv_silu_kernel(const __half* __restrict__ xp,
                      const float* __restrict__ cw,
                      const float* __restrict__ cb,
                      __half* __restrict__ uhi)
{
    const int nc4 = INNER / 4;
    int gid = blockIdx.x * blockDim.x + threadIdx.x;
    if (gid >= nc4 * (NTOK / CT)) return;
    int c4 = gid % nc4;
    int tb = gid / nc4;
    int c  = c4 * 4;
    int t0 = tb * CT;
    int l0 = t0 & (SEQLEN - 1);

    float4 bias = *(const float4*)(cb + c);
    float4 w0 = *(const float4*)(cw + (c + 0) * D_CONV);
    float4 w1 = *(const float4*)(cw + (c + 1) * D_CONV);
    float4 w2 = *(const float4*)(cw + (c + 2) * D_CONV);
    float4 w3 = *(const float4*)(cw + (c + 3) * D_CONV);
    const float* pw0 = (const float*)&w0;
    const float* pw1 = (const float*)&w1;
    const float* pw2 = (const float*)&w2;
    const float* pw3 = (const float*)&w3;

    const float4 zero = make_float4(0.f, 0.f, 0.f, 0.f);
    auto ldrow = [&](int t) -> float4 {
        uint2 raw = *(const uint2*)(xp + (size_t)t * INNER + c);
        __half2 a = *(__half2*)&raw.x;
        __half2 b = *(__half2*)&raw.y;
        float2 fa = __half22float2(a), fb = __half22float2(b);
        return make_float4(fa.x, fa.y, fb.x, fb.y);
    };

    float4 x0 = (l0 >= 3) ? ldrow(t0 - 3) : zero;
    float4 x1 = (l0 >= 2) ? ldrow(t0 - 2) : zero;
    float4 x2 = (l0 >= 1) ? ldrow(t0 - 1) : zero;

    #pragma unroll
    for (int j = 0; j < CT; ++j) {
        float4 x3 = ldrow(t0 + j);
        float4 acc = bias;
        acc.x = fmaf(pw0[0], x0.x, acc.x); acc.x = fmaf(pw0[1], x1.x, acc.x);
        acc.x = fmaf(pw0[2], x2.x, acc.x); acc.x = fmaf(pw0[3], x3.x, acc.x);
        acc.y = fmaf(pw1[0], x0.y, acc.y); acc.y = fmaf(pw1[1], x1.y, acc.y);
        acc.y = fmaf(pw1[2], x2.y, acc.y); acc.y = fmaf(pw1[3], x3.y, acc.y);
        acc.z = fmaf(pw2[0], x0.z, acc.z); acc.z = fmaf(pw2[1], x1.z, acc.z);
        acc.z = fmaf(pw2[2], x2.z, acc.z); acc.z = fmaf(pw2[3], x3.z, acc.z);
        acc.w = fmaf(pw3[0], x0.w, acc.w); acc.w = fmaf(pw3[1], x1.w, acc.w);
        acc.w = fmaf(pw3[2], x2.w, acc.w); acc.w = fmaf(pw3[3], x3.w, acc.w);

        float4 v = make_float4(siluf(acc.x), siluf(acc.y), siluf(acc.z), siluf(acc.w));
        store_h4(uhi + (size_t)(t0 + j) * INNER + c, v);

        x0 = x1; x1 = x2; x2 = x3;
    }
}

// ---------------- scan pass 1 (scalar fast path for uniform A) ----------------
__global__ __launch_bounds__(256)
void scan_pass1(const __half* __restrict__ dt, const __half* __restrict__ u,
                const float* __restrict__ A_log, const float* __restrict__ Bp,
                float* __restrict__ hend, float* __restrict__ hend_s,
                float* __restrict__ sdtb)
{
    int idx = blockIdx.x * blockDim.x + threadIdx.x;
    int d = idx % INNER;
    int c = (idx / INNER) & (NCHUNK - 1);
    int b = idx / (INNER * NCHUNK);
    int bc = b * NCHUNK + c;
    int t0 = b * SEQLEN + c * CHUNK;

    float a0 = A_log[d * D_STATE];
    bool uni = true;
    #pragma unroll
    for (int n = 1; n < D_STATE; ++n)
        uni = uni && (A_log[d * D_STATE + n] == a0);

    float sdt = 0.0f;
    if (uni) {
        const float Av0 = -__expf(a0);
        float w = 0.0f;
        for (int j = 0; j < CHUNK; ++j) {
            size_t off = (size_t)(t0 + j) * INNER + d;
            float dtv = __half2float(dt[off]);
            float uv  = __half2float(u[off]);
            sdt += dtv;
            w = fmaf(__expf(dtv * Av0), w, dtv * uv);
        }
        hend_s[(size_t)bc * INNER + d] = w;
    } else {
        float Av[D_STATE], Bv[D_STATE], h[D_STATE];
        #pragma unroll
        for (int n = 0; n < D_STATE; ++n) {
            Av[n] = -__expf(A_log[d * D_STATE + n]);
            Bv[n] = Bp[d * D_STATE + n];
            h[n]  = 0.0f;
        }
        for (int j = 0; j < CHUNK; ++j) {
            size_t off = (size_t)(t0 + j) * INNER + d;
            float dtv = __half2float(dt[off]);
            float uv  = __half2float(u[off]);
            sdt += dtv;
            float du = dtv * uv;
            #pragma unroll
            for (int n = 0; n < D_STATE; ++n)
                h[n] = fmaf(__expf(dtv * Av[n]), h[n], du * Bv[n]);
        }
        #pragma unroll
        for (int n = 0; n < D_STATE; ++n)
            hend[(size_t)(bc * D_STATE + n) * INNER + d] = h[n];
    }
    sdtb[(size_t)bc * INNER + d] = sdt;
}

// ---------------- scan fixup ----------------
__global__ __launch_bounds__(256)
void scan_fix(const float* __restrict__ A_log,
              const float* __restrict__ hend, const float* __restrict__ hend_s,
              const float* __restrict__ sdtb,
              float* __restrict__ h0buf, float* __restrict__ h0_s)
{
    int idx = blockIdx.x * blockDim.x + threadIdx.x;
    if (idx >= BATCH * INNER * D_STATE) return;
    int d = idx % INNER;
    int n = (idx / INNER) % D_STATE;
    int b = idx / (INNER * D_STATE);

    float a0 = A_log[d * D_STATE];
    bool uni = true;
    #pragma unroll
    for (int k = 1; k < D_STATE; ++k)
        uni = uni && (A_log[d * D_STATE + k] == a0);

    if (uni) {
        if (n != 0) return;
        float Av = -__expf(a0);
        float w = 0.0f;
        for (int c = 0; c < NCHUNK; ++c) {
            int bc = b * NCHUNK + c;
            h0_s[(size_t)bc * INNER + d] = w;
            float s = sdtb[(size_t)bc * INNER + d];
            w = fmaf(__expf(Av * s), w, hend_s[(size_t)bc * INNER + d]);
        }
    } else {
        float Av = -__expf(A_log[d * D_STATE + n]);
        float h = 0.0f;
        const size_t nd = (size_t)n * INNER + d;
        for (int c = 0; c < NCHUNK; ++c) {
            int bc = b * NCHUNK + c;
            h0buf[(size_t)bc * D_STATE * INNER + nd] = h;
            float s = sdtb[(size_t)bc * INNER + d];
            h = fmaf(__expf(Av * s), h, hend[(size_t)bc * D_STATE * INNER + nd]);
        }
    }
}

// ---------------- scan pass 2 (scalar fast path; gate fp16) ----------------
__global__ __launch_bounds__(256)
void scan_pass2(const __half* __restrict__ dt, const __half* __restrict__ u,
                const __half* __restrict__ zh,
                const float* __restrict__ A_log, const float* __restrict__ Bp,
                const float* __restrict__ Cp, const float* __restrict__ Dp,
                const float* __restrict__ h0buf, const float* __restrict__ h0_s,
                __half* __restrict__ yghi)
{
    int idx = blockIdx.x * blockDim.x + threadIdx.x;
    int d = idx % INNER;
    int c = (idx / INNER) & (NCHUNK - 1);
    int b = idx / (INNER * NCHUNK);
    int bc = b * NCHUNK + c;
    int t0 = b * SEQLEN + c * CHUNK;
    float Dv = Dp[d];

    float a0 = A_log[d * D_STATE];
    bool uni = true;
    #pragma unroll
    for (int n = 1; n < D_STATE; ++n)
        uni = uni && (A_log[d * D_STATE + n] == a0);

    if (uni) {
        const float Av0 = -__expf(a0);
        float bcsum = 0.0f;
        #pragma unroll
        for (int n = 0; n < D_STATE; ++n)
            bcsum = fmaf(Bp[d * D_STATE + n], Cp[d * D_STATE + n], bcsum);
        float w = h0_s[(size_t)bc * INNER + d];
        for (int j = 0; j < CHUNK; ++j) {
            size_t off = (size_t)(t0 + j) * INNER + d;
            float dtv = __half2float(dt[off]);
            float uv  = __half2float(u[off]);
            w = fmaf(__expf(dtv * Av0), w, dtv * uv);
            float z = __half2float(zh[off]);
            float v = fmaf(bcsum, w, Dv * uv) * siluf(z);
            yghi[off] = __float2half_rn(v);
        }
    } else {
        float Av[D_STATE], Bv[D_STATE], Cv[D_STATE], h[D_STATE];
        #pragma unroll
        for (int n = 0; n < D_STATE; ++n) {
            Av[n] = -__expf(A_log[d * D_STATE + n]);
            Bv[n] = Bp[d * D_STATE + n];
            Cv[n] = Cp[d * D_STATE + n];
            h[n]  = h0buf[(size_t)(bc * D_STATE + n) * INNER + d];
        }
        for (int j = 0; j < CHUNK; ++j) {
            size_t off = (size_t)(t0 + j) * INNER + d;
            float dtv = __half2float(dt[off]);
            float uv  = __half2float(u[off]);
            float du  = dtv * uv;
            float y = 0.0f;
            #pragma unroll
            for (int n = 0; n < D_STATE; ++n) {
                h[n] = fmaf(__expf(dtv * Av[n]), h[n], du * Bv[n]);
                y = fmaf(h[n], Cv[n], y);
            }
            float z = __half2float(zh[off]);
            float v = (y + Dv * uv) * siluf(z);
            yghi[off] = __float2half_rn(v);
        }
    }
}

// ---------------- launcher ----------------
extern "C" void kernel_launch(void* const* d_in, const int* in_sizes, int n_in,
                              void* d_out, int out_size)
{
    const float* hidden    = (const float*)d_in[0];
    const float* in_proj_w = (const float*)d_in[1];
    const float* out_proj_w= (const float*)d_in[2];
    const float* dt_proj_w = (const float*)d_in[3];
    const float* dt_proj_b = (const float*)d_in[4];
    const float* conv_w    = (const float*)d_in[5];
    const float* conv_b    = (const float*)d_in[6];
    const float* A_log     = (const float*)d_in[7];
    const float* B_param   = (const float*)d_in[8];
    const float* C_param   = (const float*)d_in[9];
    const float* D_param   = (const float*)d_in[10];
    const float* dt_bias   = (const float*)d_in[11];
    float* out = (float*)d_out;

    float *hend, *h0, *hend_s, *h0_s, *sdt;
    __half *xp_h, *z_h, *hid_hi, *wi_hi, *wd_hi, *wo_hi, *u_hi, *dt_h, *yg_hi;
    cudaGetSymbolAddress((void**)&hend,   g_hend);
    cudaGetSymbolAddress((void**)&h0,     g_h0);
    cudaGetSymbolAddress((void**)&hend_s, g_hend_s);
    cudaGetSymbolAddress((void**)&h0_s,   g_h0_s);
    cudaGetSymbolAddress((void**)&sdt,    g_sdt);
    cudaGetSymbolAddress((void**)&xp_h,   g_xp_h);
    cudaGetSymbolAddress((void**)&z_h,    g_z_h);
    cudaGetSymbolAddress((void**)&hid_hi, g_hid_hi);
    cudaGetSymbolAddress((void**)&wi_hi,  g_wi_hi);
    cudaGetSymbolAddress((void**)&wd_hi,  g_wd_hi);
    cudaGetSymbolAddress((void**)&wo_hi,  g_wo_hi);
    cudaGetSymbolAddress((void**)&u_hi,   g_u_hi);
    cudaGetSymbolAddress((void**)&dt_h,   g_dt_h);
    cudaGetSymbolAddress((void**)&yg_hi,  g_yg_hi);

    cudaFuncSetAttribute(gemm_fp16x<1>,
                         cudaFuncAttributeMaxDynamicSharedMemorySize, SMEM_G);
    cudaFuncSetAttribute(gemm_fp16x<2>,
                         cudaFuncAttributeMaxDynamicSharedMemorySize, SMEM_G);
    cudaFuncSetAttribute(gemm_out64,
                         cudaFuncAttributeMaxDynamicSharedMemorySize, OSMEM);

    // 0) fp16 converts (merged)
    split_all<<<SPL_TOT4 / 256, 256>>>(hidden, in_proj_w, dt_proj_w, out_proj_w,
                                       hid_hi, wi_hi, wd_hi, wo_hi);

    // 1) in_proj (x1, merged proj+gate; fp16 epilogue both halves)
    {
        dim3 grid(N2 / 256, NTOK / 128);
        gemm_fp16x<2><<<grid, 256, SMEM_G>>>(hid_hi, wi_hi,
                                             xp_h, z_h, NTOK, D_MODEL,
                                             nullptr, nullptr);
    }
    // 2) depthwise conv + SiLU -> u_hi (fp16 in/out)
    conv_silu_kernel<<<(INNER / 4) * (NTOK / CT) / 256, 256>>>(xp_h, conv_w, conv_b, u_hi);
    // 3) dt_proj + softplus (x1) -> fp16
    {
        dim3 grid(INNER / 256, NTOK / 128);
        gemm_fp16x<1><<<grid, 256, SMEM_G>>>(u_hi, wd_hi,
                                             dt_h, nullptr, NTOK, INNER,
                                             dt_proj_b, dt_bias);
    }
    // 4) chunked selective scan (scalar fast path; exact for uniform A)
    {
        int n1 = BATCH * NCHUNK * INNER;
        scan_pass1<<<n1 / 256, 256>>>(dt_h, u_hi, A_log, B_param,
                                      hend, hend_s, sdt);
        scan_fix<<<(BATCH * INNER * D_STATE) / 256, 256>>>(A_log, hend, hend_s,
                                                           sdt, h0, h0_s);
        scan_pass2<<<n1 / 256, 256>>>(dt_h, u_hi, z_h, A_log, B_param, C_param,
                                      D_param, h0, h0_s, yg_hi);
    }
    // 5) out_proj (x1, 64x64 tiles)
    {
        dim3 grid(D_MODEL / 64, NTOK / 64);
        gemm_out64<<<grid, 256, OSMEM>>>(yg_hi, wo_hi, out, NTOK, D_MODEL, INNER);
    }
}

// round 16
// speedup vs baseline: 1.1078x; 1.1078x over previous
#include <cuda_runtime.h>
#include <cuda_fp16.h>
#include <math.h>
#include <stdint.h>

// ---------------- problem constants ----------------
#define D_MODEL 768
#define D_STATE 16
#define D_CONV  4
#define INNER   1536
#define N2      (2*INNER)     // 3072
#define BATCH   2
#define SEQLEN  2048
#define NTOK    (BATCH*SEQLEN)  // 4096
#define NCHUNK  64
#define CHUNK   (SEQLEN/NCHUNK) // 32
#define CT      16              // conv timesteps per thread

// ---------------- scratch (static device globals; no allocation) ----------------
__device__ float g_hend[BATCH*NCHUNK*D_STATE*INNER];   // general fallback
__device__ float g_h0  [BATCH*NCHUNK*D_STATE*INNER];   // general fallback
__device__ float g_hend_s[BATCH*NCHUNK*INNER];         // scalar fast path
__device__ float g_h0_s  [BATCH*NCHUNK*INNER];         // scalar fast path
__device__ float g_sdt [BATCH*NCHUNK*INNER];

// fp16 tensors
__device__ __half g_xp_h  [NTOK * INNER];
__device__ __half g_z_h   [NTOK * INNER];
__device__ __half g_hid_hi[NTOK * D_MODEL];
__device__ __half g_wi_hi [N2 * D_MODEL];
__device__ __half g_wd_hi [INNER * INNER];
__device__ __half g_wo_hi [D_MODEL * INNER];
__device__ __half g_u_hi  [NTOK * INNER];
__device__ __half g_dt_h  [NTOK * INNER];
__device__ __half g_yg_hi [NTOK * INNER];

// ---------------- helpers ----------------
__device__ __forceinline__ float siluf(float x) {
    return x * (1.0f / (1.0f + __expf(-x)));
}
__device__ __forceinline__ float softplusf(float x) {
    return fmaxf(x, 0.0f) + log1pf(__expf(-fabsf(x)));
}
__device__ __forceinline__ uint32_t smem_u32(const void* p) {
    uint32_t a;
    asm("{ .reg .u64 t; cvta.to.shared.u64 t, %1; cvt.u32.u64 %0, t; }"
        : "=r"(a) : "l"(p));
    return a;
}
__device__ __forceinline__ void cp16(uint32_t s, const void* g) {
    asm volatile("cp.async.cg.shared.global [%0], [%1], 16;\n" :: "r"(s), "l"(g));
}
__device__ __forceinline__ void cp_commit() {
    asm volatile("cp.async.commit_group;\n");
}
template<int N> __device__ __forceinline__ void cp_wait() {
    asm volatile("cp.async.wait_group %0;\n" :: "n"(N));
}
__device__ __forceinline__ void ldm_x4(uint32_t a, uint32_t* r) {
    asm volatile("ldmatrix.sync.aligned.m8n8.x4.shared.b16 {%0,%1,%2,%3}, [%4];"
                 : "=r"(r[0]), "=r"(r[1]), "=r"(r[2]), "=r"(r[3]) : "r"(a));
}
__device__ __forceinline__ void mma_fp16(float* d, const uint32_t* a,
                                         uint32_t b0, uint32_t b1) {
    asm volatile(
        "mma.sync.aligned.m16n8k16.row.col.f32.f16.f16.f32 "
        "{%0,%1,%2,%3}, {%4,%5,%6,%7}, {%8,%9}, {%0,%1,%2,%3};\n"
        : "+f"(d[0]), "+f"(d[1]), "+f"(d[2]), "+f"(d[3])
        : "r"(a[0]), "r"(a[1]), "r"(a[2]), "r"(a[3]), "r"(b0), "r"(b1));
}
__device__ __forceinline__ void store_h4(__half* p, float4 v) {
    __half2 a = __floats2half2_rn(v.x, v.y);
    __half2 b = __floats2half2_rn(v.z, v.w);
    uint2 o;
    o.x = *(uint32_t*)&a;
    o.y = *(uint32_t*)&b;
    *(uint2*)p = o;
}

// ---------------- merged split kernel (all plain fp32 -> fp16) ----------------
#define SPL_N0 (NTOK*D_MODEL)
#define SPL_N1 (N2*D_MODEL)
#define SPL_N2 (INNER*INNER)
#define SPL_N3 (D_MODEL*INNER)
#define SPL_TOT4 ((SPL_N0+SPL_N1+SPL_N2+SPL_N3)/4)

__device__ __forceinline__ void cvt4_hi(const float* s, __half* h) {
    float4 v = *(const float4*)s;
    store_h4(h, v);
}

__global__ __launch_bounds__(256)
void split_all(const float* __restrict__ hidden, const float* __restrict__ wi,
               const float* __restrict__ wd, const float* __restrict__ wo,
               __half* __restrict__ hid_hi, __half* __restrict__ wi_hi,
               __half* __restrict__ wd_hi, __half* __restrict__ wo_hi)
{
    int idx = (blockIdx.x * blockDim.x + threadIdx.x) * 4;
    if (idx < SPL_N0) {
        cvt4_hi(hidden + idx, hid_hi + idx);
    } else if ((idx -= SPL_N0) < SPL_N1) {
        cvt4_hi(wi + idx, wi_hi + idx);
    } else if ((idx -= SPL_N1) < SPL_N2) {
        cvt4_hi(wd + idx, wd_hi + idx);
    } else if ((idx -= SPL_N2) < SPL_N3) {
        cvt4_hi(wo + idx, wo_hi + idx);
    }
}

// ---------------- fp16 x1 NT GEMM (128x128 tiles, 2-stage, wtile 64x32) ----------------
// EPI 1: softplus(x+b1+b2) -> fp16 into Ca (stride INNER)
// EPI 2: in_proj mixed: cols < INNER -> fp16 Ca; cols >= INNER -> fp16 Cb
#define TILE_B 16384
#define SMEM_G (2 * 2 * TILE_B)   // 65536

template<int EPI>
__global__ __launch_bounds__(256)
void gemm_fp16x(const __half* __restrict__ Ahi, const __half* __restrict__ Bhi,
                __half* __restrict__ Ca, __half* __restrict__ Cb,
                int M, int K,
                const float* __restrict__ b1, const float* __restrict__ b2)
{
    extern __shared__ char smem[];
    const uint32_t sb = smem_u32(smem);

    const int tid  = threadIdx.x;
    const int wid  = tid >> 5;
    const int lane = tid & 31;
    const int wm   = wid & 1;
    const int wn   = wid >> 1;
    const int g    = lane >> 3;
    const int lr   = lane & 7;

    const int row0 = blockIdx.y * 128;
    const int col0 = blockIdx.x * 128;

    const __half* srcA = Ahi + (size_t)row0 * K;
    const __half* srcB = Bhi + (size_t)col0 * K;

    float acc[4][4][4];
    #pragma unroll
    for (int mt = 0; mt < 4; ++mt)
        #pragma unroll
        for (int nt = 0; nt < 4; ++nt)
            #pragma unroll
            for (int r = 0; r < 4; ++r) acc[mt][nt][r] = 0.0f;

    auto load_stage = [&](int s, int kc) {
        const __half* gp[2] = { srcA + kc, srcB + kc };
        #pragma unroll
        for (int t = 0; t < 2; ++t) {
            uint32_t dst = sb + (uint32_t)(s * 2 + t) * TILE_B;
            const __half* src = gp[t];
            #pragma unroll
            for (int i = 0; i < 4; ++i) {
                int c = tid + i * 256;
                int r = c >> 3, ch = c & 7;
                cp16(dst + r * 128 + ((ch ^ (r & 7)) << 4),
                     src + (size_t)r * K + ch * 8);
            }
        }
    };

    const int KT = K / 64;
    load_stage(0, 0);
    cp_commit();

    for (int kt = 0; kt < KT; ++kt) {
        if (kt + 1 < KT) {
            load_stage((kt + 1) & 1, (kt + 1) * 64);
            cp_commit();
            cp_wait<1>();
        } else {
            cp_wait<0>();
        }
        __syncthreads();

        const uint32_t st  = sb + (uint32_t)(kt & 1) * 2 * TILE_B;
        const uint32_t sAh = st;
        const uint32_t sBh = st + TILE_B;

        #pragma unroll
        for (int k16 = 0; k16 < 4; ++k16) {
            const int c0 = k16 * 2;
            const int arow_off = ((g & 1) << 3) + lr;
            const int ach = c0 + (g >> 1);
            const int brow_off = ((g >> 1) << 3) + lr;
            const int bch = c0 + (g & 1);

            uint32_t ah[4][4];
            #pragma unroll
            for (int mt = 0; mt < 4; ++mt) {
                int row = wm * 64 + mt * 16 + arow_off;
                uint32_t off = row * 128 + (((ach ^ (row & 7))) << 4);
                ldm_x4(sAh + off, ah[mt]);
            }
            uint32_t bh[4][2];
            #pragma unroll
            for (int nn = 0; nn < 2; ++nn) {
                int row = wn * 32 + nn * 16 + brow_off;
                uint32_t off = row * 128 + (((bch ^ (row & 7))) << 4);
                uint32_t t4[4];
                ldm_x4(sBh + off, t4);
                bh[nn*2][0] = t4[0]; bh[nn*2][1] = t4[1];
                bh[nn*2+1][0] = t4[2]; bh[nn*2+1][1] = t4[3];
            }
            #pragma unroll
            for (int mt = 0; mt < 4; ++mt)
                #pragma unroll
                for (int nt = 0; nt < 4; ++nt)
                    mma_fp16(acc[mt][nt], ah[mt], bh[nt][0], bh[nt][1]);
        }
        __syncthreads();
    }

    const int qr = lane >> 2;
    const int qc = (lane & 3) * 2;
    #pragma unroll
    for (int mt = 0; mt < 4; ++mt) {
        #pragma unroll
        for (int nt = 0; nt < 4; ++nt) {
            int gr = row0 + wm * 64 + mt * 16 + qr;
            int gc = col0 + wn * 32 + nt * 8 + qc;
            float v0 = acc[mt][nt][0], v1 = acc[mt][nt][1];
            float v2 = acc[mt][nt][2], v3 = acc[mt][nt][3];
            if (EPI == 1) {
                float e0 = b1[gc] + b2[gc];
                float e1 = b1[gc + 1] + b2[gc + 1];
                *(__half2*)&Ca[(size_t)gr * INNER + gc] =
                    __floats2half2_rn(softplusf(v0 + e0), softplusf(v1 + e1));
                *(__half2*)&Ca[(size_t)(gr + 8) * INNER + gc] =
                    __floats2half2_rn(softplusf(v2 + e0), softplusf(v3 + e1));
            } else {  // EPI == 2
                __half* Cp = (gc < INNER) ? Ca : Cb;
                int g2 = (gc < INNER) ? gc : gc - INNER;
                *(__half2*)&Cp[(size_t)gr * INNER + g2] = __floats2half2_rn(v0, v1);
                *(__half2*)&Cp[(size_t)(gr + 8) * INNER + g2] = __floats2half2_rn(v2, v3);
            }
        }
    }
}

// ---------------- out_proj GEMM: 64x64 tiles, x1, 3-stage, 3 CTAs/SM ----------------
#define OTILE 8192
#define OSTAGE (2 * OTILE)
#define OSMEM (3 * OSTAGE)     // 49152

__global__ __launch_bounds__(256, 3)
void gemm_out64(const __half* __restrict__ Ahi, const __half* __restrict__ Bhi,
                float* __restrict__ C, int M, int N, int K)
{
    extern __shared__ char smem[];
    const uint32_t sb = smem_u32(smem);

    const int tid  = threadIdx.x;
    const int wid  = tid >> 5;
    const int lane = tid & 31;
    const int wm   = wid & 1;
    const int wn   = wid >> 1;
    const int g    = lane >> 3;
    const int lr   = lane & 7;

    const int row0 = blockIdx.y * 64;
    const int col0 = blockIdx.x * 64;

    const __half* sA  = Ahi + (size_t)row0 * K;
    const __half* sBh = Bhi + (size_t)col0 * K;

    float acc[2][2][4];
    #pragma unroll
    for (int mt = 0; mt < 2; ++mt)
        #pragma unroll
        for (int nt = 0; nt < 2; ++nt)
            #pragma unroll
            for (int r = 0; r < 4; ++r) acc[mt][nt][r] = 0.0f;

    auto load_stage = [&](int s, int kc) {
        uint32_t base = sb + (uint32_t)s * OSTAGE;
        const __half* gp[2] = { sA + kc, sBh + kc };
        #pragma unroll
        for (int t = 0; t < 2; ++t) {
            uint32_t dst = base + (uint32_t)t * OTILE;
            const __half* src = gp[t];
            #pragma unroll
            for (int i = 0; i < 2; ++i) {
                int c = tid + i * 256;
                int r = c >> 3, ch = c & 7;
                cp16(dst + r * 128 + ((ch ^ (r & 7)) << 4),
                     src + (size_t)r * K + ch * 8);
            }
        }
    };

    const int KT = K / 64;   // 24
    load_stage(0, 0); cp_commit();
    load_stage(1, 64); cp_commit();

    int st = 0;
    for (int kt = 0; kt < KT; ++kt) {
        if (kt + 1 < KT) cp_wait<1>(); else cp_wait<0>();
        __syncthreads();
        if (kt + 2 < KT) {
            int ns = st + 2; if (ns >= 3) ns -= 3;
            load_stage(ns, (kt + 2) * 64);
            cp_commit();
        }

        const uint32_t base = sb + (uint32_t)st * OSTAGE;
        const uint32_t mA  = base;
        const uint32_t mBh = base + OTILE;

        #pragma unroll
        for (int k16 = 0; k16 < 4; ++k16) {
            const int c0 = k16 * 2;
            const int arow_off = ((g & 1) << 3) + lr;
            const int ach = c0 + (g >> 1);
            const int brow_off = ((g >> 1) << 3) + lr;
            const int bch = c0 + (g & 1);

            uint32_t ah[2][4];
            #pragma unroll
            for (int mt = 0; mt < 2; ++mt) {
                int row = wm * 32 + mt * 16 + arow_off;
                uint32_t off = row * 128 + (((ach ^ (row & 7))) << 4);
                ldm_x4(mA + off, ah[mt]);
            }
            uint32_t bh[2][2];
            {
                int row = wn * 16 + brow_off;
                uint32_t off = row * 128 + (((bch ^ (row & 7))) << 4);
                uint32_t t4[4];
                ldm_x4(mBh + off, t4);
                bh[0][0] = t4[0]; bh[0][1] = t4[1];
                bh[1][0] = t4[2]; bh[1][1] = t4[3];
            }
            #pragma unroll
            for (int mt = 0; mt < 2; ++mt)
                #pragma unroll
                for (int nt = 0; nt < 2; ++nt)
                    mma_fp16(acc[mt][nt], ah[mt], bh[nt][0], bh[nt][1]);
        }
        if (++st == 3) st = 0;
    }

    const int qr = lane >> 2;
    const int qc = (lane & 3) * 2;
    #pragma unroll
    for (int mt = 0; mt < 2; ++mt) {
        #pragma unroll
        for (int nt = 0; nt < 2; ++nt) {
            int gr = row0 + wm * 32 + mt * 16 + qr;
            int gc = col0 + wn * 16 + nt * 8 + qc;
            *(float2*)&C[(size_t)gr * N + gc] =
                make_float2(acc[mt][nt][0], acc[mt][nt][1]);
            *(float2*)&C[(size_t)(gr + 8) * N + gc] =
                make_float2(acc[mt][nt][2], acc[mt][nt][3]);
        }
    }
}

// ---------------- conv: 4 ch x 16 t, sliding window, fp16 in/out ----------------
__global__ __launch_bounds__(256)
void conv_silu_kernel(const __half* __restrict__ xp,
                      const float* __restrict__ cw,
                      const float* __restrict__ cb,
                      __half* __restrict__ uhi)
{
    const int nc4 = INNER / 4;
    int gid = blockIdx.x * blockDim.x + threadIdx.x;
    if (gid >= nc4 * (NTOK / CT)) return;
    int c4 = gid % nc4;
    int tb = gid / nc4;
    int c  = c4 * 4;
    int t0 = tb * CT;
    int l0 = t0 & (SEQLEN - 1);

    float4 bias = *(const float4*)(cb + c);
    float4 w0 = *(const float4*)(cw + (c + 0) * D_CONV);
    float4 w1 = *(const float4*)(cw + (c + 1) * D_CONV);
    float4 w2 = *(const float4*)(cw + (c + 2) * D_CONV);
    float4 w3 = *(const float4*)(cw + (c + 3) * D_CONV);
    const float* pw0 = (const float*)&w0;
    const float* pw1 = (const float*)&w1;
    const float* pw2 = (const float*)&w2;
    const float* pw3 = (const float*)&w3;

    const float4 zero = make_float4(0.f, 0.f, 0.f, 0.f);
    auto ldrow = [&](int t) -> float4 {
        uint2 raw = *(const uint2*)(xp + (size_t)t * INNER + c);
        __half2 a = *(__half2*)&raw.x;
        __half2 b = *(__half2*)&raw.y;
        float2 fa = __half22float2(a), fb = __half22float2(b);
        return make_float4(fa.x, fa.y, fb.x, fb.y);
    };

    float4 x0 = (l0 >= 3) ? ldrow(t0 - 3) : zero;
    float4 x1 = (l0 >= 2) ? ldrow(t0 - 2) : zero;
    float4 x2 = (l0 >= 1) ? ldrow(t0 - 1) : zero;

    #pragma unroll
    for (int j = 0; j < CT; ++j) {
        float4 x3 = ldrow(t0 + j);
        float4 acc = bias;
        acc.x = fmaf(pw0[0], x0.x, acc.x); acc.x = fmaf(pw0[1], x1.x, acc.x);
        acc.x = fmaf(pw0[2], x2.x, acc.x); acc.x = fmaf(pw0[3], x3.x, acc.x);
        acc.y = fmaf(pw1[0], x0.y, acc.y); acc.y = fmaf(pw1[1], x1.y, acc.y);
        acc.y = fmaf(pw1[2], x2.y, acc.y); acc.y = fmaf(pw1[3], x3.y, acc.y);
        acc.z = fmaf(pw2[0], x0.z, acc.z); acc.z = fmaf(pw2[1], x1.z, acc.z);
        acc.z = fmaf(pw2[2], x2.z, acc.z); acc.z = fmaf(pw2[3], x3.z, acc.z);
        acc.w = fmaf(pw3[0], x0.w, acc.w); acc.w = fmaf(pw3[1], x1.w, acc.w);
        acc.w = fmaf(pw3[2], x2.w, acc.w); acc.w = fmaf(pw3[3], x3.w, acc.w);

        float4 v = make_float4(siluf(acc.x), siluf(acc.y), siluf(acc.z), siluf(acc.w));
        store_h4(uhi + (size_t)(t0 + j) * INNER + c, v);

        x0 = x1; x1 = x2; x2 = x3;
    }
}

// ---------------- scan pass 1 (scalar fast path for uniform A) ----------------
__global__ __launch_bounds__(256)
void scan_pass1(const __half* __restrict__ dt, const __half* __restrict__ u,
                const float* __restrict__ A_log, const float* __restrict__ Bp,
                float* __restrict__ hend, float* __restrict__ hend_s,
                float* __restrict__ sdtb)
{
    int idx = blockIdx.x * blockDim.x + threadIdx.x;
    int d = idx % INNER;
    int c = (idx / INNER) & (NCHUNK - 1);
    int b = idx / (INNER * NCHUNK);
    int bc = b * NCHUNK + c;
    int t0 = b * SEQLEN + c * CHUNK;

    float a0 = A_log[d * D_STATE];
    bool uni = true;
    #pragma unroll
    for (int n = 1; n < D_STATE; ++n)
        uni = uni && (A_log[d * D_STATE + n] == a0);

    float sdt = 0.0f;
    if (uni) {
        const float Av0 = -__expf(a0);
        float w = 0.0f;
        for (int j = 0; j < CHUNK; ++j) {
            size_t off = (size_t)(t0 + j) * INNER + d;
            float dtv = __half2float(dt[off]);
            float uv  = __half2float(u[off]);
            sdt += dtv;
            w = fmaf(__expf(dtv * Av0), w, dtv * uv);
        }
        hend_s[(size_t)bc * INNER + d] = w;
    } else {
        float Av[D_STATE], Bv[D_STATE], h[D_STATE];
        #pragma unroll
        for (int n = 0; n < D_STATE; ++n) {
            Av[n] = -__expf(A_log[d * D_STATE + n]);
            Bv[n] = Bp[d * D_STATE + n];
            h[n]  = 0.0f;
        }
        for (int j = 0; j < CHUNK; ++j) {
            size_t off = (size_t)(t0 + j) * INNER + d;
            float dtv = __half2float(dt[off]);
            float uv  = __half2float(u[off]);
            sdt += dtv;
            float du = dtv * uv;
            #pragma unroll
            for (int n = 0; n < D_STATE; ++n)
                h[n] = fmaf(__expf(dtv * Av[n]), h[n], du * Bv[n]);
        }
        #pragma unroll
        for (int n = 0; n < D_STATE; ++n)
            hend[(size_t)(bc * D_STATE + n) * INNER + d] = h[n];
    }
    sdtb[(size_t)bc * INNER + d] = sdt;
}

// ---------------- scan fixup ----------------
__global__ __launch_bounds__(256)
void scan_fix(const float* __restrict__ A_log,
              const float* __restrict__ hend, const float* __restrict__ hend_s,
              const float* __restrict__ sdtb,
              float* __restrict__ h0buf, float* __restrict__ h0_s)
{
    int idx = blockIdx.x * blockDim.x + threadIdx.x;
    if (idx >= BATCH * INNER * D_STATE) return;
    int d = idx % INNER;
    int n = (idx / INNER) % D_STATE;
    int b = idx / (INNER * D_STATE);

    float a0 = A_log[d * D_STATE];
    bool uni = true;
    #pragma unroll
    for (int k = 1; k < D_STATE; ++k)
        uni = uni && (A_log[d * D_STATE + k] == a0);

    if (uni) {
        if (n != 0) return;
        float Av = -__expf(a0);
        float w = 0.0f;
        for (int c = 0; c < NCHUNK; ++c) {
            int bc = b * NCHUNK + c;
            h0_s[(size_t)bc * INNER + d] = w;
            float s = sdtb[(size_t)bc * INNER + d];
            w = fmaf(__expf(Av * s), w, hend_s[(size_t)bc * INNER + d]);
        }
    } else {
        float Av = -__expf(A_log[d * D_STATE + n]);
        float h = 0.0f;
        const size_t nd = (size_t)n * INNER + d;
        for (int c = 0; c < NCHUNK; ++c) {
            int bc = b * NCHUNK + c;
            h0buf[(size_t)bc * D_STATE * INNER + nd] = h;
            float s = sdtb[(size_t)bc * INNER + d];
            h = fmaf(__expf(Av * s), h, hend[(size_t)bc * D_STATE * INNER + nd]);
        }
    }
}

// ---------------- scan pass 2 (scalar fast path; gate fp16) ----------------
__global__ __launch_bounds__(256)
void scan_pass2(const __half* __restrict__ dt, const __half* __restrict__ u,
                const __half* __restrict__ zh,
                const float* __restrict__ A_log, const float* __restrict__ Bp,
                const float* __restrict__ Cp, const float* __restrict__ Dp,
                const float* __restrict__ h0buf, const float* __restrict__ h0_s,
                __half* __restrict__ yghi)
{
    int idx = blockIdx.x * blockDim.x + threadIdx.x;
    int d = idx % INNER;
    int c = (idx / INNER) & (NCHUNK - 1);
    int b = idx / (INNER * NCHUNK);
    int bc = b * NCHUNK + c;
    int t0 = b * SEQLEN + c * CHUNK;
    float Dv = Dp[d];

    float a0 = A_log[d * D_STATE];
    bool uni = true;
    #pragma unroll
    for (int n = 1; n < D_STATE; ++n)
        uni = uni && (A_log[d * D_STATE + n] == a0);

    if (uni) {
        const float Av0 = -__expf(a0);
        float bcsum = 0.0f;
        #pragma unroll
        for (int n = 0; n < D_STATE; ++n)
            bcsum = fmaf(Bp[d * D_STATE + n], Cp[d * D_STATE + n], bcsum);
        float w = h0_s[(size_t)bc * INNER + d];
        for (int j = 0; j < CHUNK; ++j) {
            size_t off = (size_t)(t0 + j) * INNER + d;
            float dtv = __half2float(dt[off]);
            float uv  = __half2float(u[off]);
            w = fmaf(__expf(dtv * Av0), w, dtv * uv);
            float z = __half2float(zh[off]);
            float v = fmaf(bcsum, w, Dv * uv) * siluf(z);
            yghi[off] = __float2half_rn(v);
        }
    } else {
        float Av[D_STATE], Bv[D_STATE], Cv[D_STATE], h[D_STATE];
        #pragma unroll
        for (int n = 0; n < D_STATE; ++n) {
            Av[n] = -__expf(A_log[d * D_STATE + n]);
            Bv[n] = Bp[d * D_STATE + n];
            Cv[n] = Cp[d * D_STATE + n];
            h[n]  = h0buf[(size_t)(bc * D_STATE + n) * INNER + d];
        }
        for (int j = 0; j < CHUNK; ++j) {
            size_t off = (size_t)(t0 + j) * INNER + d;
            float dtv = __half2float(dt[off]);
            float uv  = __half2float(u[off]);
            float du  = dtv * uv;
            float y = 0.0f;
            #pragma unroll
            for (int n = 0; n < D_STATE; ++n) {
                h[n] = fmaf(__expf(dtv * Av[n]), h[n], du * Bv[n]);
                y = fmaf(h[n], Cv[n], y);
            }
            float z = __half2float(zh[off]);
            float v = (y + Dv * uv) * siluf(z);
            yghi[off] = __float2half_rn(v);
        }
    }
}

// ---------------- launcher ----------------
extern "C" void kernel_launch(void* const* d_in, const int* in_sizes, int n_in,
                              void* d_out, int out_size)
{
    const float* hidden    = (const float*)d_in[0];
    const float* in_proj_w = (const float*)d_in[1];
    const float* out_proj_w= (const float*)d_in[2];
    const float* dt_proj_w = (const float*)d_in[3];
    const float* dt_proj_b = (const float*)d_in[4];
    const float* conv_w    = (const float*)d_in[5];
    const float* conv_b    = (const float*)d_in[6];
    const float* A_log     = (const float*)d_in[7];
    const float* B_param   = (const float*)d_in[8];
    const float* C_param   = (const float*)d_in[9];
    const float* D_param   = (const float*)d_in[10];
    const float* dt_bias   = (const float*)d_in[11];
    float* out = (float*)d_out;

    float *hend, *h0, *hend_s, *h0_s, *sdt;
    __half *xp_h, *z_h, *hid_hi, *wi_hi, *wd_hi, *wo_hi, *u_hi, *dt_h, *yg_hi;
    cudaGetSymbolAddress((void**)&hend,   g_hend);
    cudaGetSymbolAddress((void**)&h0,     g_h0);
    cudaGetSymbolAddress((void**)&hend_s, g_hend_s);
    cudaGetSymbolAddress((void**)&h0_s,   g_h0_s);
    cudaGetSymbolAddress((void**)&sdt,    g_sdt);
    cudaGetSymbolAddress((void**)&xp_h,   g_xp_h);
    cudaGetSymbolAddress((void**)&z_h,    g_z_h);
    cudaGetSymbolAddress((void**)&hid_hi, g_hid_hi);
    cudaGetSymbolAddress((void**)&wi_hi,  g_wi_hi);
    cudaGetSymbolAddress((void**)&wd_hi,  g_wd_hi);
    cudaGetSymbolAddress((void**)&wo_hi,  g_wo_hi);
    cudaGetSymbolAddress((void**)&u_hi,   g_u_hi);
    cudaGetSymbolAddress((void**)&dt_h,   g_dt_h);
    cudaGetSymbolAddress((void**)&yg_hi,  g_yg_hi);

    cudaFuncSetAttribute(gemm_fp16x<1>,
                         cudaFuncAttributeMaxDynamicSharedMemorySize, SMEM_G);
    cudaFuncSetAttribute(gemm_fp16x<2>,
                         cudaFuncAttributeMaxDynamicSharedMemorySize, SMEM_G);
    cudaFuncSetAttribute(gemm_out64,
                         cudaFuncAttributeMaxDynamicSharedMemorySize, OSMEM);

    // 0) fp16 converts (merged)
    split_all<<<SPL_TOT4 / 256, 256>>>(hidden, in_proj_w, dt_proj_w, out_proj_w,
                                       hid_hi, wi_hi, wd_hi, wo_hi);

    // 1) in_proj (x1, merged proj+gate; fp16 epilogue both halves)
    {
        dim3 grid(N2 / 128, NTOK / 128);
        gemm_fp16x<2><<<grid, 256, SMEM_G>>>(hid_hi, wi_hi,
                                             xp_h, z_h, NTOK, D_MODEL,
                                             nullptr, nullptr);
    }
    // 2) depthwise conv + SiLU -> u_hi (fp16 in/out)
    conv_silu_kernel<<<(INNER / 4) * (NTOK / CT) / 256, 256>>>(xp_h, conv_w, conv_b, u_hi);
    // 3) dt_proj + softplus (x1) -> fp16
    {
        dim3 grid(INNER / 128, NTOK / 128);
        gemm_fp16x<1><<<grid, 256, SMEM_G>>>(u_hi, wd_hi,
                                             dt_h, nullptr, NTOK, INNER,
                                             dt_proj_b, dt_bias);
    }
    // 4) chunked selective scan (scalar fast path; exact for uniform A)
    {
        int n1 = BATCH * NCHUNK * INNER;
        scan_pass1<<<n1 / 256, 256>>>(dt_h, u_hi, A_log, B_param,
                                      hend, hend_s, sdt);
        scan_fix<<<(BATCH * INNER * D_STATE) / 256, 256>>>(A_log, hend, hend_s,
                                                           sdt, h0, h0_s);
        scan_pass2<<<n1 / 256, 256>>>(dt_h, u_hi, z_h, A_log, B_param, C_param,
                                      D_param, h0, h0_s, yg_hi);
    }
    // 5) out_proj (x1, 64x64 tiles)
    {
        dim3 grid(D_MODEL / 64, NTOK / 64);
        gemm_out64<<<grid, 256, OSMEM>>>(yg_hi, wo_hi, out, NTOK, D_MODEL, INNER);
    }
}